// round 9
// baseline (speedup 1.0000x reference)
#include <cuda_runtime.h>
#include <cuda_bf16.h>
#include <math.h>
#include <stdint.h>

#define HW 4096
#define NB 8
#define ASTR 56       // A smem row stride (halves)
#define BSTR 136      // B smem row stride (halves)
#define STAGES 4

// per-stage smem layout (bytes)
#define A_HI_OFF 0
#define A_LO_OFF (128 * ASTR * 2)                 // 14336
#define B_HI_OFF (2 * 128 * ASTR * 2)             // 28672
#define B_LO_OFF (B_HI_OFF + 32 * BSTR * 2)       // 37376
#define STAGE_BYTES (B_LO_OFF + 32 * BSTR * 2)    // 46080
#define GEMM_SMEM (STAGES * STAGE_BYTES)          // 184320

// ---------------- scratch (device globals) ---------------------------------
__device__ float g_y[NB * 1024 * HW];                       // concat(cv1,cv2) fp32
__device__ __nv_bfloat16 g_x0h[NB * 512 * HW], g_x0l[NB * 512 * HW];     // split input x
__device__ __nv_bfloat16 g_xh1[NB * 1024 * HW], g_xl1[NB * 1024 * HW];   // cv1 input
__device__ __nv_bfloat16 g_xh2[NB * 1024 * HW], g_xl2[NB * 1024 * HW];   // cv2 input
__device__ __nv_bfloat16 g_bh [NB * 1024 * HW], g_bl [NB * 1024 * HW];   // c1 input (dw out)
__device__ __nv_bfloat16 g_gh [NB * 1024 * HW], g_gl [NB * 1024 * HW];   // cvend input (gated)
__device__ __nv_bfloat16 g_wsh[256 * 512],   g_wsl[256 * 512];
__device__ __nv_bfloat16 g_w1h[512 * 1024],  g_w1l[512 * 1024];
__device__ __nv_bfloat16 g_w2h[512 * 1024],  g_w2l[512 * 1024];
__device__ __nv_bfloat16 g_weh[512 * 1024],  g_wel[512 * 1024];
__device__ __nv_bfloat16 g_wch[1024 * 1024], g_wcl[1024 * 1024];

// ---------------- helpers ---------------------------------------------------
__device__ __forceinline__ uint32_t smem_u32(const void* p) {
    uint32_t a;
    asm("{ .reg .u64 t; cvta.to.shared.u64 t, %1; cvt.u32.u64 %0, t; }" : "=r"(a) : "l"(p));
    return a;
}
#define CP16(dst_u32, src_ptr) \
    asm volatile("cp.async.cg.shared.global [%0], [%1], 16;" \
        :: "r"(dst_u32), "l"(src_ptr) : "memory")
#define CP_COMMIT() asm volatile("cp.async.commit_group;" ::: "memory")
#define CP_WAIT(n)  asm volatile("cp.async.wait_group %0;" :: "n"(n) : "memory")

__device__ __forceinline__ void ldsm4(unsigned* r, const __nv_bfloat16* p) {
    unsigned a = smem_u32(p);
    asm volatile("ldmatrix.sync.aligned.m8n8.x4.shared.b16 {%0,%1,%2,%3},[%4];"
        : "=r"(r[0]), "=r"(r[1]), "=r"(r[2]), "=r"(r[3]) : "r"(a));
}
__device__ __forceinline__ void ldsm4t(unsigned* r, const __nv_bfloat16* p) {
    unsigned a = smem_u32(p);
    asm volatile("ldmatrix.sync.aligned.m8n8.x4.trans.shared.b16 {%0,%1,%2,%3},[%4];"
        : "=r"(r[0]), "=r"(r[1]), "=r"(r[2]), "=r"(r[3]) : "r"(a));
}
__device__ __forceinline__ void mma16816(float* d, const unsigned* a, const unsigned* b) {
    asm volatile("mma.sync.aligned.m16n8k16.row.col.f32.bf16.bf16.f32 "
        "{%0,%1,%2,%3},{%4,%5,%6,%7},{%8,%9},{%0,%1,%2,%3};"
        : "+f"(d[0]), "+f"(d[1]), "+f"(d[2]), "+f"(d[3])
        : "r"(a[0]), "r"(a[1]), "r"(a[2]), "r"(a[3]), "r"(b[0]), "r"(b[1]));
}
__device__ __forceinline__ void pack2(float a, float b, uint32_t& h, uint32_t& l) {
    __nv_bfloat16 ha = __float2bfloat16(a), hb = __float2bfloat16(b);
    __nv_bfloat162 hp(ha, hb);
    __nv_bfloat162 lp(__float2bfloat16(a - __bfloat162float(ha)),
                      __float2bfloat16(b - __bfloat162float(hb)));
    h = *(uint32_t*)&hp; l = *(uint32_t*)&lp;
}

// ---------------- fp32 -> bf16 hi/lo split (weights + input) ---------------
__global__ void split2(const float* __restrict__ in, __nv_bfloat16* __restrict__ hi,
                       __nv_bfloat16* __restrict__ lo, int n4)
{
    int i = blockIdx.x * blockDim.x + threadIdx.x;
    if (i >= n4) return;
    float4 v = ((const float4*)in)[i];
    uint32_t h0, l0, h1, l1;
    pack2(v.x, v.y, h0, l0);
    pack2(v.z, v.w, h1, l1);
    ((uint32_t*)hi)[i * 2] = h0;     ((uint32_t*)hi)[i * 2 + 1] = h1;
    ((uint32_t*)lo)[i * 2] = l0;     ((uint32_t*)lo)[i * 2 + 1] = l1;
}

// ---------------- GEMM: pre-split bf16, cp.async 4-stage, mma.sync ---------
// D[m][n] = act(sum_k W[m,k] * X[k,n] + bias[m]),  m=outC, n=hw
// EPI: 0 = fp32 store to Yf (at coff); 1 = split2 dup store (sta);
//      2 = gate with Ygate then split store (c1)
template<int ACT, int EPI>
__global__ void __launch_bounds__(256, 1)
gemm_pre(const __nv_bfloat16* __restrict__ Ahi, const __nv_bfloat16* __restrict__ Alo,
         const __nv_bfloat16* __restrict__ Bhi, const __nv_bfloat16* __restrict__ Blo,
         const float* __restrict__ bias, float* __restrict__ Yf,
         const float* __restrict__ Ygate,
         __nv_bfloat16* __restrict__ o1h, __nv_bfloat16* __restrict__ o1l,
         __nv_bfloat16* __restrict__ o2h, __nv_bfloat16* __restrict__ o2l,
         int K, int outCtot, int coff)
{
    extern __shared__ __align__(16) char smem[];
    const uint32_t smU = smem_u32(smem);
    const int tid = threadIdx.x;
    const int lane = tid & 31, warp = tid >> 5;
    const int wm = warp >> 2, wn = warp & 3;
    const int m0 = blockIdx.x * 128;
    const int hw0 = blockIdx.y * 128;
    const int bz = blockIdx.z;
    const size_t xoff = (size_t)bz * K * HW;
    const int iters = K / 32;

    auto load_stage = [&](int buf, int c) {
        const uint32_t sbase = smU + buf * STAGE_BYTES;
#pragma unroll
        for (int e = 0; e < 2; e++) {
            int idx = tid * 2 + e;                 // 0..511
            int row = idx >> 2, kg = (idx & 3) * 8;
            size_t g = (size_t)(m0 + row) * K + c * 32 + kg;
            uint32_t so = (uint32_t)(row * ASTR + kg) * 2;
            CP16(sbase + A_HI_OFF + so, Ahi + g);
            CP16(sbase + A_LO_OFF + so, Alo + g);
        }
#pragma unroll
        for (int e = 0; e < 2; e++) {
            int idx = tid * 2 + e;
            int kr = idx >> 4, ng = (idx & 15) * 8;
            size_t g = xoff + (size_t)(c * 32 + kr) * HW + hw0 + ng;
            uint32_t so = (uint32_t)(kr * BSTR + ng) * 2;
            CP16(sbase + B_HI_OFF + so, Bhi + g);
            CP16(sbase + B_LO_OFF + so, Blo + g);
        }
    };

    float acc[4][4][4];
#pragma unroll
    for (int i = 0; i < 4; i++)
#pragma unroll
        for (int j = 0; j < 4; j++)
#pragma unroll
            for (int q = 0; q < 4; q++) acc[i][j][q] = 0.f;

    const int arow = lane & 15;
    const int acol8 = (lane >> 4) << 3;
    const int bkrow = (lane & 7) + ((lane & 8) ? 8 : 0);
    const int bcol8 = (lane & 16) ? 8 : 0;

#pragma unroll
    for (int p = 0; p < STAGES; p++) {
        load_stage(p, p);
        CP_COMMIT();
    }

    for (int it = 0; it < iters; it++) {
        CP_WAIT(STAGES - 1);
        __syncthreads();
        const int buf = it & (STAGES - 1);
        const __nv_bfloat16* sAh = (const __nv_bfloat16*)(smem + buf * STAGE_BYTES + A_HI_OFF);
        const __nv_bfloat16* sAl = (const __nv_bfloat16*)(smem + buf * STAGE_BYTES + A_LO_OFF);
        const __nv_bfloat16* sBh = (const __nv_bfloat16*)(smem + buf * STAGE_BYTES + B_HI_OFF);
        const __nv_bfloat16* sBl = (const __nv_bfloat16*)(smem + buf * STAGE_BYTES + B_LO_OFF);

#pragma unroll
        for (int ks = 0; ks < 2; ks++) {
            unsigned ah[4][4], al[4][4], bh[4][2], bl[4][2];
            const int acol = ks * 16 + acol8;
#pragma unroll
            for (int mt = 0; mt < 4; mt++) {
                int m = wm * 64 + mt * 16 + arow;
                ldsm4(ah[mt], sAh + m * ASTR + acol);
                ldsm4(al[mt], sAl + m * ASTR + acol);
            }
            const int krow = ks * 16 + bkrow;
#pragma unroll
            for (int q = 0; q < 2; q++) {
                int j0 = wn * 32 + q * 16 + bcol8;
                unsigned r[4];
                ldsm4t(r, sBh + krow * BSTR + j0);
                bh[q * 2][0] = r[0]; bh[q * 2][1] = r[1];
                bh[q * 2 + 1][0] = r[2]; bh[q * 2 + 1][1] = r[3];
                ldsm4t(r, sBl + krow * BSTR + j0);
                bl[q * 2][0] = r[0]; bl[q * 2][1] = r[1];
                bl[q * 2 + 1][0] = r[2]; bl[q * 2 + 1][1] = r[3];
            }
#pragma unroll
            for (int mt = 0; mt < 4; mt++)
#pragma unroll
                for (int nt = 0; nt < 4; nt++) {
                    mma16816(acc[mt][nt], ah[mt], bh[nt]);
                    mma16816(acc[mt][nt], ah[mt], bl[nt]);
                    mma16816(acc[mt][nt], al[mt], bh[nt]);
                }
        }
        __syncthreads();
        if (it + STAGES < iters) load_stage(buf, it + STAGES);
        CP_COMMIT();
    }

    // ---------------- epilogue ----------------
    const int r0 = lane >> 2, c0 = (lane & 3) * 2;
#pragma unroll
    for (int mt = 0; mt < 4; mt++) {
        int mA = m0 + wm * 64 + mt * 16 + r0;
        int mB = mA + 8;
        float bvA = bias[mA], bvB = bias[mB];
#pragma unroll
        for (int nt = 0; nt < 4; nt++) {
            int n = hw0 + wn * 32 + nt * 8 + c0;
            float v0 = acc[mt][nt][0] + bvA;
            float v1 = acc[mt][nt][1] + bvA;
            float v2 = acc[mt][nt][2] + bvB;
            float v3 = acc[mt][nt][3] + bvB;
            if (ACT) {
                v0 = v0 / (1.f + expf(-v0));
                v1 = v1 / (1.f + expf(-v1));
                v2 = v2 / (1.f + expf(-v2));
                v3 = v3 / (1.f + expf(-v3));
            }
            size_t oA = (size_t)bz * outCtot * HW + (size_t)(coff + mA) * HW + n;
            size_t oB = (size_t)bz * outCtot * HW + (size_t)(coff + mB) * HW + n;
            if (EPI == 0) {
                *(float2*)(Yf + oA) = make_float2(v0, v1);
                *(float2*)(Yf + oB) = make_float2(v2, v3);
            } else if (EPI == 1) {
                uint32_t h, l;
                pack2(v0, v1, h, l);
                *(uint32_t*)(o1h + oA) = h; *(uint32_t*)(o1l + oA) = l;
                *(uint32_t*)(o2h + oA) = h; *(uint32_t*)(o2l + oA) = l;
                pack2(v2, v3, h, l);
                *(uint32_t*)(o1h + oB) = h; *(uint32_t*)(o1l + oB) = l;
                *(uint32_t*)(o2h + oB) = h; *(uint32_t*)(o2l + oB) = l;
            } else {
                float2 yA = *(const float2*)(Ygate + oA);
                float2 yB = *(const float2*)(Ygate + oB);
                uint32_t h, l;
                pack2(v0 * yA.x, v1 * yA.y, h, l);
                *(uint32_t*)(o1h + oA) = h; *(uint32_t*)(o1l + oA) = l;
                pack2(v2 * yB.x, v3 * yB.y, h, l);
                *(uint32_t*)(o1h + oB) = h; *(uint32_t*)(o1l + oB) = l;
            }
        }
    }
}

// ---------------- fused dual-branch SPPF pooling (split I/O) ---------------
__global__ void __launch_bounds__(256)
pool_both(const __nv_bfloat16* __restrict__ xh, const __nv_bfloat16* __restrict__ xl,
          __nv_bfloat16* __restrict__ o1h, __nv_bfloat16* __restrict__ o1l,
          __nv_bfloat16* __restrict__ o2h, __nv_bfloat16* __restrict__ o2l)
{
    extern __shared__ float sp[];
    float* sx = sp;
    float* si = sp + 4096;
    float* t1 = sp + 8192;
    float* t2 = sp + 12288;
    const int ch = blockIdx.x, b = blockIdx.y;
    const int tid = threadIdx.x;
    const size_t src = ((size_t)b * 1024 + ch) * HW;

    for (int i = tid; i < 4096; i += 256) {
        float v = __bfloat162float(xh[src + i]) + __bfloat162float(xl[src + i]);
        sx[i] = v; si[i] = v;
    }
    __syncthreads();

    for (int s = 0; s < 3; s++) {
        for (int i = tid; i < 4096; i += 256) {
            int c = i & 63;
            const float* row = &si[i - c];
            float mx = -INFINITY, sm = 0.f;
#pragma unroll
            for (int d = -2; d <= 2; d++) {
                int cc = c + d;
                if (cc >= 0 && cc < 64) { float v = row[cc]; mx = fmaxf(mx, v); sm += v; }
            }
            t1[i] = mx; t2[i] = sm;
        }
        __syncthreads();
        size_t dst = ((size_t)b * 1024 + (s + 1) * 256 + ch) * HW;
        for (int i = tid; i < 4096; i += 256) {
            int c = i & 63, r = i >> 6;
            float mx = -INFINITY, sm = 0.f;
#pragma unroll
            for (int d = -2; d <= 2; d++) {
                int rr = r + d;
                if (rr >= 0 && rr < 64) { mx = fmaxf(mx, t1[rr * 64 + c]); sm += t2[rr * 64 + c]; }
            }
            float v = 0.9f * mx + 0.004f * sm;
            si[i] = v;
            __nv_bfloat16 h = __float2bfloat16(v);
            o1h[dst + i] = h;
            o1l[dst + i] = __float2bfloat16(v - __bfloat162float(h));
        }
        __syncthreads();
    }

    for (int i = tid; i < 4096; i += 256) si[i] = sx[i];
    __syncthreads();

    for (int s = 0; s < 3; s++) {
        for (int i = tid; i < 4096; i += 256) {
            int c = i & 63;
            const float* row = &si[i - c];
            float se = 0.f, sex = 0.f;
#pragma unroll
            for (int d = -2; d <= 2; d++) {
                int cc = c + d;
                if (cc >= 0 && cc < 64) {
                    float v = row[cc];
                    float e = expf(v);
                    se += e; sex += e * v;
                }
            }
            t1[i] = se; t2[i] = sex;
        }
        __syncthreads();
        size_t dst = ((size_t)b * 1024 + (s + 1) * 256 + ch) * HW;
        for (int i = tid; i < 4096; i += 256) {
            int c = i & 63, r = i >> 6;
            float den = 0.f, num = 0.f;
#pragma unroll
            for (int d = -2; d <= 2; d++) {
                int rr = r + d;
                if (rr >= 0 && rr < 64) { den += t1[rr * 64 + c]; num += t2[rr * 64 + c]; }
            }
            float v = num / (den + 1e-6f);
            si[i] = v;
            __nv_bfloat16 h = __float2bfloat16(v);
            o2h[dst + i] = h;
            o2l[dst + i] = __float2bfloat16(v - __bfloat162float(h));
        }
        __syncthreads();
    }
}

// ---------------- fused LSKA depthwise chain (fp32 in, split out) ----------
__global__ void __launch_bounds__(256)
dw_fused(const float* __restrict__ y,
         const float* __restrict__ w1, const float* __restrict__ b1,
         const float* __restrict__ w2, const float* __restrict__ b2,
         const float* __restrict__ w3, const float* __restrict__ b3,
         const float* __restrict__ w4, const float* __restrict__ b4,
         __nv_bfloat16* __restrict__ oh, __nv_bfloat16* __restrict__ ol)
{
    __shared__ float s0[4096], s1[4096];
    const int ch = blockIdx.x, b = blockIdx.y;
    const int tid = threadIdx.x;
    const size_t off = ((size_t)b * 1024 + ch) * HW;

    for (int i = tid; i < 4096; i += 256) s0[i] = y[off + i];
    __syncthreads();

    {
        float wa = w1[ch * 3], wb = w1[ch * 3 + 1], wc = w1[ch * 3 + 2], bb = b1[ch];
        for (int i = tid; i < 4096; i += 256) {
            int c = i & 63;
            const float* row = &s0[i - c];
            float acc = bb + wb * row[c];
            if (c >= 1)  acc = fmaf(wa, row[c - 1], acc);
            if (c <= 62) acc = fmaf(wc, row[c + 1], acc);
            s1[i] = acc;
        }
    }
    __syncthreads();
    {
        float wa = w2[ch * 3], wb = w2[ch * 3 + 1], wc = w2[ch * 3 + 2], bb = b2[ch];
        for (int i = tid; i < 4096; i += 256) {
            int r = i >> 6;
            float acc = bb + wb * s1[i];
            if (r >= 1)  acc = fmaf(wa, s1[i - 64], acc);
            if (r <= 62) acc = fmaf(wc, s1[i + 64], acc);
            s0[i] = acc;
        }
    }
    __syncthreads();
    {
        float wa = w3[ch * 3], wb = w3[ch * 3 + 1], wc = w3[ch * 3 + 2], bb = b3[ch];
        for (int i = tid; i < 4096; i += 256) {
            int c = i & 63;
            const float* row = &s0[i - c];
            float acc = bb + wb * row[c];
            if (c >= 2)  acc = fmaf(wa, row[c - 2], acc);
            if (c <= 61) acc = fmaf(wc, row[c + 2], acc);
            s1[i] = acc;
        }
    }
    __syncthreads();
    {
        float wa = w4[ch * 3], wb = w4[ch * 3 + 1], wc = w4[ch * 3 + 2], bb = b4[ch];
        for (int i = tid; i < 4096; i += 256) {
            int r = i >> 6;
            float acc = bb + wb * s1[i];
            if (r >= 2)  acc = fmaf(wa, s1[i - 128], acc);
            if (r <= 61) acc = fmaf(wc, s1[i + 128], acc);
            __nv_bfloat16 h = __float2bfloat16(acc);
            oh[off + i] = h;
            ol[off + i] = __float2bfloat16(acc - __bfloat162float(h));
        }
    }
}

// ---------------- launch ----------------------------------------------------
extern "C" void kernel_launch(void* const* d_in, const int* in_sizes, int n_in,
                              void* d_out, int out_size)
{
    const float* x       = (const float*)d_in[0];
    const float* w_sta   = (const float*)d_in[1];
    const float* b_sta   = (const float*)d_in[2];
    const float* w_cv1   = (const float*)d_in[3];
    const float* b_cv1   = (const float*)d_in[4];
    const float* w_cv2   = (const float*)d_in[5];
    const float* b_cv2   = (const float*)d_in[6];
    const float* w_cvend = (const float*)d_in[7];
    const float* b_cvend = (const float*)d_in[8];
    const float* w_dwh   = (const float*)d_in[9];
    const float* b_dwh   = (const float*)d_in[10];
    const float* w_dwv   = (const float*)d_in[11];
    const float* b_dwv   = (const float*)d_in[12];
    const float* w_ddwh  = (const float*)d_in[13];
    const float* b_ddwh  = (const float*)d_in[14];
    const float* w_ddwv  = (const float*)d_in[15];
    const float* b_ddwv  = (const float*)d_in[16];
    const float* w_c1    = (const float*)d_in[17];
    const float* b_c1    = (const float*)d_in[18];

    float *y;
    __nv_bfloat16 *x0h, *x0l, *xh1, *xl1, *xh2, *xl2, *bh, *bl, *gh, *gl;
    __nv_bfloat16 *wsh, *wsl, *w1h, *w1l, *w2h, *w2l, *weh, *wel, *wch, *wcl;
    cudaGetSymbolAddress((void**)&y,   g_y);
    cudaGetSymbolAddress((void**)&x0h, g_x0h); cudaGetSymbolAddress((void**)&x0l, g_x0l);
    cudaGetSymbolAddress((void**)&xh1, g_xh1); cudaGetSymbolAddress((void**)&xl1, g_xl1);
    cudaGetSymbolAddress((void**)&xh2, g_xh2); cudaGetSymbolAddress((void**)&xl2, g_xl2);
    cudaGetSymbolAddress((void**)&bh,  g_bh);  cudaGetSymbolAddress((void**)&bl,  g_bl);
    cudaGetSymbolAddress((void**)&gh,  g_gh);  cudaGetSymbolAddress((void**)&gl,  g_gl);
    cudaGetSymbolAddress((void**)&wsh, g_wsh); cudaGetSymbolAddress((void**)&wsl, g_wsl);
    cudaGetSymbolAddress((void**)&w1h, g_w1h); cudaGetSymbolAddress((void**)&w1l, g_w1l);
    cudaGetSymbolAddress((void**)&w2h, g_w2h); cudaGetSymbolAddress((void**)&w2l, g_w2l);
    cudaGetSymbolAddress((void**)&weh, g_weh); cudaGetSymbolAddress((void**)&wel, g_wel);
    cudaGetSymbolAddress((void**)&wch, g_wch); cudaGetSymbolAddress((void**)&wcl, g_wcl);

    const int POOL_SMEM = 4 * 4096 * 4;
    cudaFuncSetAttribute(gemm_pre<1, 1>, cudaFuncAttributeMaxDynamicSharedMemorySize, GEMM_SMEM);
    cudaFuncSetAttribute(gemm_pre<1, 0>, cudaFuncAttributeMaxDynamicSharedMemorySize, GEMM_SMEM);
    cudaFuncSetAttribute(gemm_pre<0, 2>, cudaFuncAttributeMaxDynamicSharedMemorySize, GEMM_SMEM);
    cudaFuncSetAttribute(pool_both, cudaFuncAttributeMaxDynamicSharedMemorySize, POOL_SMEM);
    auto g4 = [](int n) { return (n / 4 + 255) / 256; };

    // 0) one-shot splits: network input + all weights
    split2<<<g4(NB * 512 * HW), 256>>>(x, x0h, x0l, NB * 512 * HW / 4);
    split2<<<g4(256 * 512), 256>>>(w_sta, wsh, wsl, 256 * 512 / 4);
    split2<<<g4(512 * 1024), 256>>>(w_cv1, w1h, w1l, 512 * 1024 / 4);
    split2<<<g4(512 * 1024), 256>>>(w_cv2, w2h, w2l, 512 * 1024 / 4);
    split2<<<g4(512 * 1024), 256>>>(w_cvend, weh, wel, 512 * 1024 / 4);
    split2<<<g4(1024 * 1024), 256>>>(w_c1, wch, wcl, 1024 * 1024 / 4);

    // 1) sta: 512->256 + SiLU, split-dup into (xh1,xl1) and (xh2,xl2) ch 0..255
    gemm_pre<1, 1><<<dim3(2, 32, NB), 256, GEMM_SMEM>>>(
        wsh, wsl, x0h, x0l, b_sta, nullptr, nullptr, xh1, xl1, xh2, xl2, 512, 1024, 0);

    // 2) fused dual-branch pooling (reads/writes split buffers, ch 256..1023)
    pool_both<<<dim3(256, NB), 256, POOL_SMEM>>>(xh1, xl1, xh1, xl1, xh2, xl2);

    // 3) cv1 / cv2: 1024->512 + SiLU -> fp32 concat y
    gemm_pre<1, 0><<<dim3(4, 32, NB), 256, GEMM_SMEM>>>(
        w1h, w1l, xh1, xl1, b_cv1, y, nullptr, nullptr, nullptr, nullptr, nullptr, 1024, 1024, 0);
    gemm_pre<1, 0><<<dim3(4, 32, NB), 256, GEMM_SMEM>>>(
        w2h, w2l, xh2, xl2, b_cv2, y, nullptr, nullptr, nullptr, nullptr, nullptr, 1024, 1024, 512);

    // 4) fused LSKA depthwise chain: y -> split (bh,bl)
    dw_fused<<<dim3(1024, NB), 256>>>(y, w_dwh, b_dwh, w_dwv, b_dwv,
                                      w_ddwh, b_ddwh, w_ddwv, b_ddwv, bh, bl);

    // 5) c1: 1024->1024, gate with y, split -> (gh,gl)
    gemm_pre<0, 2><<<dim3(8, 32, NB), 256, GEMM_SMEM>>>(
        wch, wcl, bh, bl, b_c1, nullptr, y, gh, gl, nullptr, nullptr, 1024, 1024, 0);

    // 6) cvend: 1024->512 + SiLU -> fp32 output
    gemm_pre<1, 0><<<dim3(4, 32, NB), 256, GEMM_SMEM>>>(
        weh, wel, gh, gl, b_cvend, (float*)d_out, nullptr, nullptr, nullptr, nullptr, nullptr,
        1024, 512, 0);
}

// round 11
// speedup vs baseline: 1.0772x; 1.0772x over previous
#include <cuda_runtime.h>
#include <cuda_bf16.h>
#include <math.h>
#include <stdint.h>

#define HW 4096
#define NB 8
#define ASTR 56       // A smem row stride (halves)
#define BSTR 136      // B smem row stride (halves)

// ---------------- scratch (device globals) ---------------------------------
__device__ float g_y[NB * 1024 * HW];                       // concat(cv1,cv2) fp32
__device__ __nv_bfloat16 g_x0h[NB * 512 * HW], g_x0l[NB * 512 * HW];     // split input x
__device__ __nv_bfloat16 g_xh1[NB * 1024 * HW], g_xl1[NB * 1024 * HW];   // cv1 input
__device__ __nv_bfloat16 g_xh2[NB * 1024 * HW], g_xl2[NB * 1024 * HW];   // cv2 input
__device__ __nv_bfloat16 g_bh [NB * 1024 * HW], g_bl [NB * 1024 * HW];   // c1 input (dw out)
__device__ __nv_bfloat16 g_gh [NB * 1024 * HW], g_gl [NB * 1024 * HW];   // cvend input (gated)
__device__ __nv_bfloat16 g_wsh[256 * 512],   g_wsl[256 * 512];
__device__ __nv_bfloat16 g_w1h[512 * 1024],  g_w1l[512 * 1024];
__device__ __nv_bfloat16 g_w2h[512 * 1024],  g_w2l[512 * 1024];
__device__ __nv_bfloat16 g_weh[512 * 1024],  g_wel[512 * 1024];
__device__ __nv_bfloat16 g_wch[1024 * 1024], g_wcl[1024 * 1024];

// ---------------- helpers ---------------------------------------------------
__device__ __forceinline__ void ldsm4(unsigned* r, const __nv_bfloat16* p) {
    unsigned a = (unsigned)__cvta_generic_to_shared(p);
    asm volatile("ldmatrix.sync.aligned.m8n8.x4.shared.b16 {%0,%1,%2,%3},[%4];"
        : "=r"(r[0]), "=r"(r[1]), "=r"(r[2]), "=r"(r[3]) : "r"(a));
}
__device__ __forceinline__ void ldsm4t(unsigned* r, const __nv_bfloat16* p) {
    unsigned a = (unsigned)__cvta_generic_to_shared(p);
    asm volatile("ldmatrix.sync.aligned.m8n8.x4.trans.shared.b16 {%0,%1,%2,%3},[%4];"
        : "=r"(r[0]), "=r"(r[1]), "=r"(r[2]), "=r"(r[3]) : "r"(a));
}
__device__ __forceinline__ void mma16816(float* d, const unsigned* a, const unsigned* b) {
    asm volatile("mma.sync.aligned.m16n8k16.row.col.f32.bf16.bf16.f32 "
        "{%0,%1,%2,%3},{%4,%5,%6,%7},{%8,%9},{%0,%1,%2,%3};"
        : "+f"(d[0]), "+f"(d[1]), "+f"(d[2]), "+f"(d[3])
        : "r"(a[0]), "r"(a[1]), "r"(a[2]), "r"(a[3]), "r"(b[0]), "r"(b[1]));
}
__device__ __forceinline__ void pack2(float a, float b, uint32_t& h, uint32_t& l) {
    __nv_bfloat16 ha = __float2bfloat16(a), hb = __float2bfloat16(b);
    __nv_bfloat162 hp(ha, hb);
    __nv_bfloat162 lp(__float2bfloat16(a - __bfloat162float(ha)),
                      __float2bfloat16(b - __bfloat162float(hb)));
    h = *(uint32_t*)&hp; l = *(uint32_t*)&lp;
}

// ---------------- fp32 -> bf16 hi/lo split (weights + input) ---------------
__global__ void split2(const float* __restrict__ in, __nv_bfloat16* __restrict__ hi,
                       __nv_bfloat16* __restrict__ lo, int n4)
{
    int i = blockIdx.x * blockDim.x + threadIdx.x;
    if (i >= n4) return;
    float4 v = ((const float4*)in)[i];
    uint32_t h0, l0, h1, l1;
    pack2(v.x, v.y, h0, l0);
    pack2(v.z, v.w, h1, l1);
    ((uint32_t*)hi)[i * 2] = h0;     ((uint32_t*)hi)[i * 2 + 1] = h1;
    ((uint32_t*)lo)[i * 2] = l0;     ((uint32_t*)lo)[i * 2 + 1] = l1;
}

// ---------------- GEMM: pre-split bf16, double-buffer + reg prefetch -------
// D[m][n] = act(sum_k W[m,k] * X[k,n] + bias[m]),  m=outC, n=hw
// EPI: 0 = fp32 store; 1 = split dup store (sta); 2 = gate with Ygate, split (c1)
template<int ACT, int EPI>
__global__ void __launch_bounds__(256, 1)
gemm_pre(const __nv_bfloat16* __restrict__ Ahi, const __nv_bfloat16* __restrict__ Alo,
         const __nv_bfloat16* __restrict__ Bhi, const __nv_bfloat16* __restrict__ Blo,
         const float* __restrict__ bias, float* __restrict__ Yf,
         const float* __restrict__ Ygate,
         __nv_bfloat16* __restrict__ o1h, __nv_bfloat16* __restrict__ o1l,
         __nv_bfloat16* __restrict__ o2h, __nv_bfloat16* __restrict__ o2l,
         int K, int outCtot, int coff)
{
    extern __shared__ __align__(16) char smraw[];
    __nv_bfloat16* sA = (__nv_bfloat16*)smraw;                 // [2 par][2 split][128][ASTR]
    __nv_bfloat16* sB = sA + 2 * 2 * 128 * ASTR;               // [2 par][2 split][32][BSTR]

    const int tid = threadIdx.x;
    const int lane = tid & 31, warp = tid >> 5;
    const int wm = warp >> 2, wn = warp & 3;
    const int m0 = blockIdx.x * 128;
    const int hw0 = blockIdx.y * 128;
    const int bz = blockIdx.z;
    const size_t xoff = (size_t)bz * K * HW;
    const int iters = K / 32;

    // per-thread load coords (uint4 = 8 halves)
    int aRow[2], aKg[2], bKr[2], bNg[2];
#pragma unroll
    for (int e = 0; e < 2; e++) {
        int i = tid + e * 256;          // 0..511
        aRow[e] = i >> 2;  aKg[e] = (i & 3) * 8;     // A: 128 rows x 32 halves
        bKr[e] = i >> 4;   bNg[e] = (i & 15) * 8;    // B: 32 rows x 128 halves
    }

    uint4 rah[2], ral[2], rbh[2], rbl[2];
    auto loadRegs = [&](int it) {
        int k0 = it * 32;
#pragma unroll
        for (int e = 0; e < 2; e++) {
            size_t ga = (size_t)(m0 + aRow[e]) * K + k0 + aKg[e];
            rah[e] = *(const uint4*)(Ahi + ga);
            ral[e] = *(const uint4*)(Alo + ga);
            size_t gb = xoff + (size_t)(k0 + bKr[e]) * HW + hw0 + bNg[e];
            rbh[e] = *(const uint4*)(Bhi + gb);
            rbl[e] = *(const uint4*)(Blo + gb);
        }
    };
    auto stsRegs = [&](int p) {
#pragma unroll
        for (int e = 0; e < 2; e++) {
            *(uint4*)(sA + ((p * 2 + 0) * 128 + aRow[e]) * ASTR + aKg[e]) = rah[e];
            *(uint4*)(sA + ((p * 2 + 1) * 128 + aRow[e]) * ASTR + aKg[e]) = ral[e];
            *(uint4*)(sB + ((p * 2 + 0) * 32 + bKr[e]) * BSTR + bNg[e]) = rbh[e];
            *(uint4*)(sB + ((p * 2 + 1) * 32 + bKr[e]) * BSTR + bNg[e]) = rbl[e];
        }
    };

    float acc[4][4][4];
#pragma unroll
    for (int i = 0; i < 4; i++)
#pragma unroll
        for (int j = 0; j < 4; j++)
#pragma unroll
            for (int q = 0; q < 4; q++) acc[i][j][q] = 0.f;

    const int arow = lane & 15;
    const int acol8 = (lane >> 4) << 3;
    const int bkrow = (lane & 7) + ((lane & 8) ? 8 : 0);
    const int bcol8 = (lane & 16) ? 8 : 0;

    loadRegs(0);
    stsRegs(0);
    if (iters > 1) loadRegs(1);
    __syncthreads();

    int p = 0;
    for (int it = 0; it < iters; it++) {
        if (it + 1 < iters) stsRegs(p ^ 1);
        if (it + 2 < iters) loadRegs(it + 2);

#pragma unroll
        for (int ks = 0; ks < 2; ks++) {
            unsigned ah[4][4], al[4][4], bh[4][2], bl[4][2];
            const int acol = ks * 16 + acol8;
#pragma unroll
            for (int mt = 0; mt < 4; mt++) {
                int m = wm * 64 + mt * 16 + arow;
                ldsm4(ah[mt], sA + ((p * 2 + 0) * 128 + m) * ASTR + acol);
                ldsm4(al[mt], sA + ((p * 2 + 1) * 128 + m) * ASTR + acol);
            }
            const int krow = ks * 16 + bkrow;
#pragma unroll
            for (int q = 0; q < 2; q++) {
                int j0 = wn * 32 + q * 16 + bcol8;
                unsigned r[4];
                ldsm4t(r, sB + ((p * 2 + 0) * 32 + krow) * BSTR + j0);
                bh[q * 2][0] = r[0]; bh[q * 2][1] = r[1];
                bh[q * 2 + 1][0] = r[2]; bh[q * 2 + 1][1] = r[3];
                ldsm4t(r, sB + ((p * 2 + 1) * 32 + krow) * BSTR + j0);
                bl[q * 2][0] = r[0]; bl[q * 2][1] = r[1];
                bl[q * 2 + 1][0] = r[2]; bl[q * 2 + 1][1] = r[3];
            }
#pragma unroll
            for (int mt = 0; mt < 4; mt++)
#pragma unroll
                for (int nt = 0; nt < 4; nt++) {
                    mma16816(acc[mt][nt], ah[mt], bh[nt]);
                    mma16816(acc[mt][nt], ah[mt], bl[nt]);
                    mma16816(acc[mt][nt], al[mt], bh[nt]);
                }
        }
        __syncthreads();
        p ^= 1;
    }

    // ---------------- epilogue ----------------
    const int r0 = lane >> 2, c0 = (lane & 3) * 2;
#pragma unroll
    for (int mt = 0; mt < 4; mt++) {
        int mA = m0 + wm * 64 + mt * 16 + r0;
        int mB = mA + 8;
        float bvA = bias[mA], bvB = bias[mB];
#pragma unroll
        for (int nt = 0; nt < 4; nt++) {
            int n = hw0 + wn * 32 + nt * 8 + c0;
            float v0 = acc[mt][nt][0] + bvA;
            float v1 = acc[mt][nt][1] + bvA;
            float v2 = acc[mt][nt][2] + bvB;
            float v3 = acc[mt][nt][3] + bvB;
            if (ACT) {
                v0 = v0 / (1.f + expf(-v0));
                v1 = v1 / (1.f + expf(-v1));
                v2 = v2 / (1.f + expf(-v2));
                v3 = v3 / (1.f + expf(-v3));
            }
            size_t oA = (size_t)bz * outCtot * HW + (size_t)(coff + mA) * HW + n;
            size_t oB = (size_t)bz * outCtot * HW + (size_t)(coff + mB) * HW + n;
            if (EPI == 0) {
                *(float2*)(Yf + oA) = make_float2(v0, v1);
                *(float2*)(Yf + oB) = make_float2(v2, v3);
            } else if (EPI == 1) {
                uint32_t h, l;
                pack2(v0, v1, h, l);
                *(uint32_t*)(o1h + oA) = h; *(uint32_t*)(o1l + oA) = l;
                *(uint32_t*)(o2h + oA) = h; *(uint32_t*)(o2l + oA) = l;
                pack2(v2, v3, h, l);
                *(uint32_t*)(o1h + oB) = h; *(uint32_t*)(o1l + oB) = l;
                *(uint32_t*)(o2h + oB) = h; *(uint32_t*)(o2l + oB) = l;
            } else {
                float2 yA = *(const float2*)(Ygate + oA);
                float2 yB = *(const float2*)(Ygate + oB);
                uint32_t h, l;
                pack2(v0 * yA.x, v1 * yA.y, h, l);
                *(uint32_t*)(o1h + oA) = h; *(uint32_t*)(o1l + oA) = l;
                pack2(v2 * yB.x, v3 * yB.y, h, l);
                *(uint32_t*)(o1h + oB) = h; *(uint32_t*)(o1l + oB) = l;
            }
        }
    }
}
#define GEMM_SMEM ((2 * 2 * 128 * ASTR + 2 * 2 * 32 * BSTR) * 2)   // 92160 B

// ---------------- fused dual-branch SPPF pooling (split I/O) ---------------
__global__ void __launch_bounds__(256)
pool_both(const __nv_bfloat16* __restrict__ xh, const __nv_bfloat16* __restrict__ xl,
          __nv_bfloat16* __restrict__ o1h, __nv_bfloat16* __restrict__ o1l,
          __nv_bfloat16* __restrict__ o2h, __nv_bfloat16* __restrict__ o2l)
{
    extern __shared__ float sp[];
    float* sx = sp;
    float* si = sp + 4096;
    float* t1 = sp + 8192;
    float* t2 = sp + 12288;
    const int ch = blockIdx.x, b = blockIdx.y;
    const int tid = threadIdx.x;
    const size_t src = ((size_t)b * 1024 + ch) * HW;

    for (int i = tid; i < 4096; i += 256) {
        float v = __bfloat162float(xh[src + i]) + __bfloat162float(xl[src + i]);
        sx[i] = v; si[i] = v;
    }
    __syncthreads();

    for (int s = 0; s < 3; s++) {
        for (int i = tid; i < 4096; i += 256) {
            int c = i & 63;
            const float* row = &si[i - c];
            float mx = -INFINITY, sm = 0.f;
#pragma unroll
            for (int d = -2; d <= 2; d++) {
                int cc = c + d;
                if (cc >= 0 && cc < 64) { float v = row[cc]; mx = fmaxf(mx, v); sm += v; }
            }
            t1[i] = mx; t2[i] = sm;
        }
        __syncthreads();
        size_t dst = ((size_t)b * 1024 + (s + 1) * 256 + ch) * HW;
        for (int i = tid; i < 4096; i += 256) {
            int c = i & 63, r = i >> 6;
            float mx = -INFINITY, sm = 0.f;
#pragma unroll
            for (int d = -2; d <= 2; d++) {
                int rr = r + d;
                if (rr >= 0 && rr < 64) { mx = fmaxf(mx, t1[rr * 64 + c]); sm += t2[rr * 64 + c]; }
            }
            float v = 0.9f * mx + 0.004f * sm;
            si[i] = v;
            __nv_bfloat16 h = __float2bfloat16(v);
            o1h[dst + i] = h;
            o1l[dst + i] = __float2bfloat16(v - __bfloat162float(h));
        }
        __syncthreads();
    }

    for (int i = tid; i < 4096; i += 256) si[i] = sx[i];
    __syncthreads();

    for (int s = 0; s < 3; s++) {
        for (int i = tid; i < 4096; i += 256) {
            int c = i & 63;
            const float* row = &si[i - c];
            float se = 0.f, sex = 0.f;
#pragma unroll
            for (int d = -2; d <= 2; d++) {
                int cc = c + d;
                if (cc >= 0 && cc < 64) {
                    float v = row[cc];
                    float e = expf(v);
                    se += e; sex += e * v;
                }
            }
            t1[i] = se; t2[i] = sex;
        }
        __syncthreads();
        size_t dst = ((size_t)b * 1024 + (s + 1) * 256 + ch) * HW;
        for (int i = tid; i < 4096; i += 256) {
            int c = i & 63, r = i >> 6;
            float den = 0.f, num = 0.f;
#pragma unroll
            for (int d = -2; d <= 2; d++) {
                int rr = r + d;
                if (rr >= 0 && rr < 64) { den += t1[rr * 64 + c]; num += t2[rr * 64 + c]; }
            }
            float v = num / (den + 1e-6f);
            si[i] = v;
            __nv_bfloat16 h = __float2bfloat16(v);
            o2h[dst + i] = h;
            o2l[dst + i] = __float2bfloat16(v - __bfloat162float(h));
        }
        __syncthreads();
    }
}

// ---------------- fused LSKA depthwise chain (fp32 in, split out) ----------
__global__ void __launch_bounds__(256)
dw_fused(const float* __restrict__ y,
         const float* __restrict__ w1, const float* __restrict__ b1,
         const float* __restrict__ w2, const float* __restrict__ b2,
         const float* __restrict__ w3, const float* __restrict__ b3,
         const float* __restrict__ w4, const float* __restrict__ b4,
         __nv_bfloat16* __restrict__ oh, __nv_bfloat16* __restrict__ ol)
{
    __shared__ float s0[4096], s1[4096];
    const int ch = blockIdx.x, b = blockIdx.y;
    const int tid = threadIdx.x;
    const size_t off = ((size_t)b * 1024 + ch) * HW;

    for (int i = tid; i < 4096; i += 256) s0[i] = y[off + i];
    __syncthreads();

    {
        float wa = w1[ch * 3], wb = w1[ch * 3 + 1], wc = w1[ch * 3 + 2], bb = b1[ch];
        for (int i = tid; i < 4096; i += 256) {
            int c = i & 63;
            const float* row = &s0[i - c];
            float acc = bb + wb * row[c];
            if (c >= 1)  acc = fmaf(wa, row[c - 1], acc);
            if (c <= 62) acc = fmaf(wc, row[c + 1], acc);
            s1[i] = acc;
        }
    }
    __syncthreads();
    {
        float wa = w2[ch * 3], wb = w2[ch * 3 + 1], wc = w2[ch * 3 + 2], bb = b2[ch];
        for (int i = tid; i < 4096; i += 256) {
            int r = i >> 6;
            float acc = bb + wb * s1[i];
            if (r >= 1)  acc = fmaf(wa, s1[i - 64], acc);
            if (r <= 62) acc = fmaf(wc, s1[i + 64], acc);
            s0[i] = acc;
        }
    }
    __syncthreads();
    {
        float wa = w3[ch * 3], wb = w3[ch * 3 + 1], wc = w3[ch * 3 + 2], bb = b3[ch];
        for (int i = tid; i < 4096; i += 256) {
            int c = i & 63;
            const float* row = &s0[i - c];
            float acc = bb + wb * row[c];
            if (c >= 2)  acc = fmaf(wa, row[c - 2], acc);
            if (c <= 61) acc = fmaf(wc, row[c + 2], acc);
            s1[i] = acc;
        }
    }
    __syncthreads();
    {
        float wa = w4[ch * 3], wb = w4[ch * 3 + 1], wc = w4[ch * 3 + 2], bb = b4[ch];
        for (int i = tid; i < 4096; i += 256) {
            int r = i >> 6;
            float acc = bb + wb * s1[i];
            if (r >= 2)  acc = fmaf(wa, s1[i - 128], acc);
            if (r <= 61) acc = fmaf(wc, s1[i + 128], acc);
            __nv_bfloat16 h = __float2bfloat16(acc);
            oh[off + i] = h;
            ol[off + i] = __float2bfloat16(acc - __bfloat162float(h));
        }
    }
}

// ---------------- launch ----------------------------------------------------
extern "C" void kernel_launch(void* const* d_in, const int* in_sizes, int n_in,
                              void* d_out, int out_size)
{
    const float* x       = (const float*)d_in[0];
    const float* w_sta   = (const float*)d_in[1];
    const float* b_sta   = (const float*)d_in[2];
    const float* w_cv1   = (const float*)d_in[3];
    const float* b_cv1   = (const float*)d_in[4];
    const float* w_cv2   = (const float*)d_in[5];
    const float* b_cv2   = (const float*)d_in[6];
    const float* w_cvend = (const float*)d_in[7];
    const float* b_cvend = (const float*)d_in[8];
    const float* w_dwh   = (const float*)d_in[9];
    const float* b_dwh   = (const float*)d_in[10];
    const float* w_dwv   = (const float*)d_in[11];
    const float* b_dwv   = (const float*)d_in[12];
    const float* w_ddwh  = (const float*)d_in[13];
    const float* b_ddwh  = (const float*)d_in[14];
    const float* w_ddwv  = (const float*)d_in[15];
    const float* b_ddwv  = (const float*)d_in[16];
    const float* w_c1    = (const float*)d_in[17];
    const float* b_c1    = (const float*)d_in[18];

    float *y;
    __nv_bfloat16 *x0h, *x0l, *xh1, *xl1, *xh2, *xl2, *bh, *bl, *gh, *gl;
    __nv_bfloat16 *wsh, *wsl, *w1h, *w1l, *w2h, *w2l, *weh, *wel, *wch, *wcl;
    cudaGetSymbolAddress((void**)&y,   g_y);
    cudaGetSymbolAddress((void**)&x0h, g_x0h); cudaGetSymbolAddress((void**)&x0l, g_x0l);
    cudaGetSymbolAddress((void**)&xh1, g_xh1); cudaGetSymbolAddress((void**)&xl1, g_xl1);
    cudaGetSymbolAddress((void**)&xh2, g_xh2); cudaGetSymbolAddress((void**)&xl2, g_xl2);
    cudaGetSymbolAddress((void**)&bh,  g_bh);  cudaGetSymbolAddress((void**)&bl,  g_bl);
    cudaGetSymbolAddress((void**)&gh,  g_gh);  cudaGetSymbolAddress((void**)&gl,  g_gl);
    cudaGetSymbolAddress((void**)&wsh, g_wsh); cudaGetSymbolAddress((void**)&wsl, g_wsl);
    cudaGetSymbolAddress((void**)&w1h, g_w1h); cudaGetSymbolAddress((void**)&w1l, g_w1l);
    cudaGetSymbolAddress((void**)&w2h, g_w2h); cudaGetSymbolAddress((void**)&w2l, g_w2l);
    cudaGetSymbolAddress((void**)&weh, g_weh); cudaGetSymbolAddress((void**)&wel, g_wel);
    cudaGetSymbolAddress((void**)&wch, g_wch); cudaGetSymbolAddress((void**)&wcl, g_wcl);

    const int POOL_SMEM = 4 * 4096 * 4;
    cudaFuncSetAttribute(gemm_pre<1, 1>, cudaFuncAttributeMaxDynamicSharedMemorySize, GEMM_SMEM);
    cudaFuncSetAttribute(gemm_pre<1, 0>, cudaFuncAttributeMaxDynamicSharedMemorySize, GEMM_SMEM);
    cudaFuncSetAttribute(gemm_pre<0, 2>, cudaFuncAttributeMaxDynamicSharedMemorySize, GEMM_SMEM);
    cudaFuncSetAttribute(pool_both, cudaFuncAttributeMaxDynamicSharedMemorySize, POOL_SMEM);
    auto g4 = [](int n) { return (n / 4 + 255) / 256; };

    // 0) one-shot splits: network input + all weights
    split2<<<g4(NB * 512 * HW), 256>>>(x, x0h, x0l, NB * 512 * HW / 4);
    split2<<<g4(256 * 512), 256>>>(w_sta, wsh, wsl, 256 * 512 / 4);
    split2<<<g4(512 * 1024), 256>>>(w_cv1, w1h, w1l, 512 * 1024 / 4);
    split2<<<g4(512 * 1024), 256>>>(w_cv2, w2h, w2l, 512 * 1024 / 4);
    split2<<<g4(512 * 1024), 256>>>(w_cvend, weh, wel, 512 * 1024 / 4);
    split2<<<g4(1024 * 1024), 256>>>(w_c1, wch, wcl, 1024 * 1024 / 4);

    // 1) sta: 512->256 + SiLU, split-dup into (xh1,xl1) and (xh2,xl2) ch 0..255
    gemm_pre<1, 1><<<dim3(2, 32, NB), 256, GEMM_SMEM>>>(
        wsh, wsl, x0h, x0l, b_sta, nullptr, nullptr, xh1, xl1, xh2, xl2, 512, 1024, 0);

    // 2) fused dual-branch pooling (split buffers, ch 256..1023)
    pool_both<<<dim3(256, NB), 256, POOL_SMEM>>>(xh1, xl1, xh1, xl1, xh2, xl2);

    // 3) cv1 / cv2: 1024->512 + SiLU -> fp32 concat y
    gemm_pre<1, 0><<<dim3(4, 32, NB), 256, GEMM_SMEM>>>(
        w1h, w1l, xh1, xl1, b_cv1, y, nullptr, nullptr, nullptr, nullptr, nullptr, 1024, 1024, 0);
    gemm_pre<1, 0><<<dim3(4, 32, NB), 256, GEMM_SMEM>>>(
        w2h, w2l, xh2, xl2, b_cv2, y, nullptr, nullptr, nullptr, nullptr, nullptr, 1024, 1024, 512);

    // 4) fused LSKA depthwise chain: y -> split (bh,bl)
    dw_fused<<<dim3(1024, NB), 256>>>(y, w_dwh, b_dwh, w_dwv, b_dwv,
                                      w_ddwh, b_ddwh, w_ddwv, b_ddwv, bh, bl);

    // 5) c1: 1024->1024, gate with y, split -> (gh,gl)
    gemm_pre<0, 2><<<dim3(8, 32, NB), 256, GEMM_SMEM>>>(
        wch, wcl, bh, bl, b_c1, nullptr, y, gh, gl, nullptr, nullptr, 1024, 1024, 0);

    // 6) cvend: 1024->512 + SiLU -> fp32 output
    gemm_pre<1, 0><<<dim3(4, 32, NB), 256, GEMM_SMEM>>>(
        weh, wel, gh, gl, b_cvend, (float*)d_out, nullptr, nullptr, nullptr, nullptr, nullptr,
        1024, 512, 0);
}